// round 1
// baseline (speedup 1.0000x reference)
#include <cuda_runtime.h>

#define BB 4
#define NN 512
#define HH 64
#define DIRD 64
#define MLPD 128
#define JT 32

// Scratch (allocation-free rule: __device__ globals)
__device__ float g_Q[BB*NN*HH];
__device__ float g_K[BB*NN*HH];
__device__ float g_V[BB*NN*HH];
__device__ float g_E[4*MLPD];
__device__ float g_c0[MLPD];

// ---------------------------------------------------------------------------
// Kernel 1: Q/K/V projections.  grid = B*N rows, 64 threads (one per column)
// ---------------------------------------------------------------------------
__global__ void qkv_kernel(const float* __restrict__ feat,
                           const float* __restrict__ Wq, const float* __restrict__ bq,
                           const float* __restrict__ Wk, const float* __restrict__ bk,
                           const float* __restrict__ Wv, const float* __restrict__ bv) {
    __shared__ float sF[HH];
    int row = blockIdx.x;
    int t = threadIdx.x;
    sF[t] = feat[row*HH + t];
    __syncthreads();
    float aq = bq[t], ak = bk[t], av = bv[t];
#pragma unroll 8
    for (int h = 0; h < HH; ++h) {
        float f = sF[h];
        aq = fmaf(f, Wq[h*HH + t], aq);
        ak = fmaf(f, Wk[h*HH + t], ak);
        av = fmaf(f, Wv[h*HH + t], av);
    }
    g_Q[row*HH + t] = aq;
    g_K[row*HH + t] = ak;
    g_V[row*HH + t] = av;
}

// ---------------------------------------------------------------------------
// Kernel 2: fold direction branch.  E = Wd @ W1[64:],  c0 = b1 + bd @ W1[64:]
// 1 block, 128 threads (one per m)
// ---------------------------------------------------------------------------
__global__ void dirfold_kernel(const float* __restrict__ Wd, const float* __restrict__ bd,
                               const float* __restrict__ W1, const float* __restrict__ b1) {
    int m = threadIdx.x;
    float e0 = 0.f, e1 = 0.f, e2 = 0.f, e3 = 0.f, c = b1[m];
#pragma unroll 8
    for (int d = 0; d < DIRD; ++d) {
        float w = W1[(HH + d)*MLPD + m];
        e0 = fmaf(Wd[0*DIRD + d], w, e0);
        e1 = fmaf(Wd[1*DIRD + d], w, e1);
        e2 = fmaf(Wd[2*DIRD + d], w, e2);
        e3 = fmaf(Wd[3*DIRD + d], w, e3);
        c  = fmaf(bd[d],          w, c);
    }
    g_E[0*MLPD + m] = e0;
    g_E[1*MLPD + m] = e1;
    g_E[2*MLPD + m] = e2;
    g_E[3*MLPD + m] = e3;
    g_c0[m] = c;
}

// ---------------------------------------------------------------------------
// Kernel 3: main.  One block per (b,i).  256 threads.
//   scores[j] = sum_m relu( (K[b,j,:]*Q[b,i,:]) @ W1a[:,m] + f[m] + g[j,m] ) * W2[m]
//   out[b,i,:] = softmax_j(scores) @ V[b]
// ---------------------------------------------------------------------------
__global__ void __launch_bounds__(256)
attn_kernel(const float* __restrict__ wind, const float* __restrict__ loc,
            const float* __restrict__ W1, const float* __restrict__ W2,
            float* __restrict__ out) {
    __shared__ __align__(16) float sW1a[HH][MLPD];   // 32 KB, [h][m]
    __shared__ float sKq[JT][HH];                    // 8 KB,  [jj][h]
    __shared__ float sE0[MLPD], sE1[MLPD], sW2[MLPD], sF[MLPD];
    __shared__ float sQ[HH];
    __shared__ float sLoc[JT*2];
    __shared__ float sScores[NN];
    __shared__ float sRed[256];
    __shared__ float sPart[4][HH];

    const int t   = threadIdx.x;
    const int blk = blockIdx.x;
    const int b   = blk >> 9;        // N = 512
    const int i   = blk & (NN - 1);
    const int bN  = b * NN;

    // Stage W1a (first 64 rows of W1, contiguous)
    {
        float* d = &sW1a[0][0];
        for (int idx = t; idx < HH*MLPD; idx += 256) d[idx] = W1[idx];
    }
    if (t < HH) sQ[t] = g_Q[(bN + i)*HH + t];
    if (t < MLPD) {
        float li0 = loc[i*2 + 0], li1 = loc[i*2 + 1];
        float w0  = wind[(bN + i)*2 + 0], w1v = wind[(bN + i)*2 + 1];
        float e0 = g_E[t], e1 = g_E[MLPD + t], e2 = g_E[2*MLPD + t], e3 = g_E[3*MLPD + t];
        sE0[t] = e0; sE1[t] = e1;
        sW2[t] = W2[t];
        sF[t]  = g_c0[t] - li0*e0 - li1*e1 + w0*e2 + w1v*e3;
    }
    __syncthreads();

    const int tx = t & 15;   // m group: columns tx*8 .. tx*8+7
    const int ty = t >> 4;   // j group: rows    ty*2 .. ty*2+1

    for (int tile = 0; tile < NN/JT; ++tile) {
        const int j0 = tile * JT;

        // Load K tile pre-scaled by Q[i]
        for (int idx = t; idx < JT*HH; idx += 256) {
            int jj = idx >> 6, h = idx & 63;
            sKq[jj][h] = g_K[(bN + j0 + jj)*HH + h] * sQ[h];
        }
        if (t < JT*2) sLoc[t] = loc[j0*2 + t];
        __syncthreads();

        float acc[2][8];
#pragma unroll
        for (int r = 0; r < 2; ++r)
#pragma unroll
            for (int c = 0; c < 8; ++c) acc[r][c] = 0.f;

#pragma unroll 4
        for (int h = 0; h < HH; ++h) {
            float4 wa = *reinterpret_cast<const float4*>(&sW1a[h][tx*8]);
            float4 wb = *reinterpret_cast<const float4*>(&sW1a[h][tx*8 + 4]);
            float wr[8] = {wa.x, wa.y, wa.z, wa.w, wb.x, wb.y, wb.z, wb.w};
            float k0 = sKq[ty*2 + 0][h];
            float k1 = sKq[ty*2 + 1][h];
#pragma unroll
            for (int c = 0; c < 8; ++c) {
                acc[0][c] = fmaf(k0, wr[c], acc[0][c]);
                acc[1][c] = fmaf(k1, wr[c], acc[1][c]);
            }
        }

        // Epilogue: add f + g, relu, dot with W2, reduce across the 16 m-groups
#pragma unroll
        for (int r = 0; r < 2; ++r) {
            int jj = ty*2 + r;
            float l0 = sLoc[jj*2 + 0], l1 = sLoc[jj*2 + 1];
            float p = 0.f;
#pragma unroll
            for (int c = 0; c < 8; ++c) {
                int m = tx*8 + c;
                float v = acc[r][c] + sF[m] + l0*sE0[m] + l1*sE1[m];
                p = fmaf(fmaxf(v, 0.f), sW2[m], p);
            }
            p += __shfl_xor_sync(0xffffffffu, p, 8);
            p += __shfl_xor_sync(0xffffffffu, p, 4);
            p += __shfl_xor_sync(0xffffffffu, p, 2);
            p += __shfl_xor_sync(0xffffffffu, p, 1);
            if (tx == 0) sScores[j0 + jj] = p;
        }
        __syncthreads();
    }

    // ---- softmax over 512 scores ----
    float s0 = sScores[t], s1 = sScores[t + 256];
    sRed[t] = fmaxf(s0, s1);
    __syncthreads();
#pragma unroll
    for (int s = 128; s > 0; s >>= 1) {
        if (t < s) sRed[t] = fmaxf(sRed[t], sRed[t + s]);
        __syncthreads();
    }
    float rmax = sRed[0];
    __syncthreads();
    float e0 = __expf(s0 - rmax);
    float e1v = __expf(s1 - rmax);
    sScores[t] = e0;
    sScores[t + 256] = e1v;
    sRed[t] = e0 + e1v;
    __syncthreads();
#pragma unroll
    for (int s = 128; s > 0; s >>= 1) {
        if (t < s) sRed[t] += sRed[t + s];
        __syncthreads();
    }
    float inv = 1.f / sRed[0];

    // ---- out = attn @ V ----
    {
        int g = t >> 6, h = t & 63;
        const float* Vb = &g_V[bN*HH];
        float a = 0.f;
#pragma unroll 4
        for (int jj = 0; jj < 128; ++jj) {
            int j = g*128 + jj;
            a = fmaf(sScores[j], Vb[j*HH + h], a);
        }
        sPart[g][h] = a;
    }
    __syncthreads();
    if (t < HH) {
        float o = (sPart[0][t] + sPart[1][t] + sPart[2][t] + sPart[3][t]) * inv;
        out[(bN + i)*HH + t] = o;
    }
}

// ---------------------------------------------------------------------------
extern "C" void kernel_launch(void* const* d_in, const int* in_sizes, int n_in,
                              void* d_out, int out_size) {
    const float* features = (const float*)d_in[0];
    const float* wind     = (const float*)d_in[1];
    const float* loc      = (const float*)d_in[2];
    const float* Wq       = (const float*)d_in[3];
    const float* bq       = (const float*)d_in[4];
    const float* Wk       = (const float*)d_in[5];
    const float* bk       = (const float*)d_in[6];
    const float* Wv       = (const float*)d_in[7];
    const float* bv       = (const float*)d_in[8];
    const float* Wd       = (const float*)d_in[9];
    const float* bd       = (const float*)d_in[10];
    const float* W1       = (const float*)d_in[11];
    const float* b1       = (const float*)d_in[12];
    const float* W2       = (const float*)d_in[13];
    // d_in[14] = b2: softmax-invariant additive constant on scores -> dropped.
    (void)in_sizes; (void)n_in; (void)out_size;

    qkv_kernel<<<BB*NN, HH>>>(features, Wq, bq, Wk, bk, Wv, bv);
    dirfold_kernel<<<1, MLPD>>>(Wd, bd, W1, b1);
    attn_kernel<<<BB*NN, 256>>>(wind, loc, W1, W2, (float*)d_out);
}

// round 3
// speedup vs baseline: 3.9159x; 3.9159x over previous
#include <cuda_runtime.h>
#include <cstdint>

#define BB 4
#define NN 512
#define HH 64
#define DIRD 64
#define MLPD 128

// Scratch (allocation-free rule: __device__ globals)
__device__ float g_Q[BB*NN*HH];
__device__ float g_K[BB*NN*HH];
__device__ float g_V[BB*NN*HH];
__device__ float g_E[4*MLPD];
__device__ float g_c0[MLPD];

// ---------------------------------------------------------------------------
__device__ __forceinline__ uint32_t f2tf32(float f) {
    uint32_t u;
    asm("cvt.rna.tf32.f32 %0, %1;" : "=r"(u) : "f"(f));
    return u;
}
__device__ __forceinline__ void mma_tf32(float d[4], const uint32_t a[4], const uint32_t b[2]) {
    asm volatile("mma.sync.aligned.m16n8k8.row.col.f32.tf32.tf32.f32 "
                 "{%0,%1,%2,%3}, {%4,%5,%6,%7}, {%8,%9}, {%0,%1,%2,%3};"
                 : "+f"(d[0]), "+f"(d[1]), "+f"(d[2]), "+f"(d[3])
                 : "r"(a[0]), "r"(a[1]), "r"(a[2]), "r"(a[3]),
                   "r"(b[0]), "r"(b[1]));
}

// ---------------------------------------------------------------------------
// Kernel 1: Q/K/V projections. 16 rows per block, W staged in smem.
// ---------------------------------------------------------------------------
#define QKV_ROWS 16
#define QKV_SMEM (3*HH*HH*4 + QKV_ROWS*HH*4)
__global__ void __launch_bounds__(256)
qkv_kernel(const float* __restrict__ feat,
           const float* __restrict__ Wq, const float* __restrict__ bq,
           const float* __restrict__ Wk, const float* __restrict__ bk,
           const float* __restrict__ Wv, const float* __restrict__ bv) {
    extern __shared__ float qs[];
    float* sWq = qs;
    float* sWk = qs + HH*HH;
    float* sWv = qs + 2*HH*HH;
    float* sF  = qs + 3*HH*HH;
    const int t = threadIdx.x;
    const int row0 = blockIdx.x * QKV_ROWS;

    for (int idx = t; idx < HH*HH; idx += 256) {
        sWq[idx] = Wq[idx];
        sWk[idx] = Wk[idx];
        sWv[idx] = Wv[idx];
    }
    for (int idx = t; idx < QKV_ROWS*HH; idx += 256)
        sF[idx] = feat[row0*HH + idx];
    __syncthreads();

    const int h = t & 63;
    const int rg = t >> 6;
    float aq[4], ak[4], av[4];
    float vbq = bq[h], vbk = bk[h], vbv = bv[h];
#pragma unroll
    for (int r = 0; r < 4; ++r) { aq[r] = vbq; ak[r] = vbk; av[r] = vbv; }
#pragma unroll 8
    for (int k = 0; k < HH; ++k) {
        float wq = sWq[k*HH + h], wk = sWk[k*HH + h], wv = sWv[k*HH + h];
#pragma unroll
        for (int r = 0; r < 4; ++r) {
            float f = sF[(rg*4 + r)*HH + k];
            aq[r] = fmaf(f, wq, aq[r]);
            ak[r] = fmaf(f, wk, ak[r]);
            av[r] = fmaf(f, wv, av[r]);
        }
    }
#pragma unroll
    for (int r = 0; r < 4; ++r) {
        int row = row0 + rg*4 + r;
        g_Q[row*HH + h] = aq[r];
        g_K[row*HH + h] = ak[r];
        g_V[row*HH + h] = av[r];
    }
}

// ---------------------------------------------------------------------------
// Kernel 2: fold direction branch. E = Wd @ W1[64:], c0 = b1 + bd @ W1[64:]
// ---------------------------------------------------------------------------
__global__ void dirfold_kernel(const float* __restrict__ Wd, const float* __restrict__ bd,
                               const float* __restrict__ W1, const float* __restrict__ b1) {
    int m = threadIdx.x;
    float e0 = 0.f, e1 = 0.f, e2 = 0.f, e3 = 0.f, c = b1[m];
#pragma unroll 8
    for (int d = 0; d < DIRD; ++d) {
        float w = W1[(HH + d)*MLPD + m];
        e0 = fmaf(Wd[0*DIRD + d], w, e0);
        e1 = fmaf(Wd[1*DIRD + d], w, e1);
        e2 = fmaf(Wd[2*DIRD + d], w, e2);
        e3 = fmaf(Wd[3*DIRD + d], w, e3);
        c  = fmaf(bd[d],          w, c);
    }
    g_E[0*MLPD + m] = e0;
    g_E[1*MLPD + m] = e1;
    g_E[2*MLPD + m] = e2;
    g_E[3*MLPD + m] = e3;
    g_c0[m] = c;
}

// ---------------------------------------------------------------------------
// Kernel 3: per-(b,i) tf32 mma.sync GEMM + in-register epilogue + softmax + AV
//   S[j,m] = sum_h K[b,j,h] * (Q[i,h]*W1[h,m]),   then relu-epilogue -> scores
// ---------------------------------------------------------------------------
#define LDA 68                      // padded row stride in 32-bit words
#define SA_OFF   0                  // 512*68*4 = 139264
#define SB_OFF   139264             // 128*68*4 = 34816
#define SC4_OFF  174080             // 4*512*4  = 8192
#define LOC_OFF  182272             // 512*8    = 4096
#define FE_OFF   186368             // 128*16   = 2048
#define RED_OFF  188416             // 256*4    = 1024
#define PART_OFF 189440             // 4*64*4   = 1024
#define SM_TOTAL 190464

__global__ void __launch_bounds__(256, 1)
attn_kernel(const float* __restrict__ wind, const float* __restrict__ loc,
            const float* __restrict__ W1, const float* __restrict__ W2,
            float* __restrict__ out) {
    extern __shared__ __align__(16) char sm[];
    uint32_t* sA   = (uint32_t*)(sm + SA_OFF);
    uint32_t* sB   = (uint32_t*)(sm + SB_OFF);
    float*    sSc4 = (float*)(sm + SC4_OFF);
    float2*   sLoc = (float2*)(sm + LOC_OFF);
    float4*   sFE  = (float4*)(sm + FE_OFF);
    float*    sRed = (float*)(sm + RED_OFF);
    float*    sPart= (float*)(sm + PART_OFF);

    const int t    = threadIdx.x;
    const int wid  = t >> 5;
    const int lane = t & 31;
    const int blk  = blockIdx.x;
    const int b    = blk >> 9;
    const int i    = blk & (NN - 1);
    const int bN   = b * NN;

    // per-i epilogue constants (f, e0, e1, W2)
    if (t < MLPD) {
        float li0 = loc[i*2 + 0], li1 = loc[i*2 + 1];
        float w0  = wind[(bN + i)*2 + 0], w1v = wind[(bN + i)*2 + 1];
        float e0 = g_E[t], e1 = g_E[MLPD + t], e2 = g_E[2*MLPD + t], e3 = g_E[3*MLPD + t];
        float f  = g_c0[t] - li0*e0 - li1*e1 + w0*e2 + w1v*e3;
        sFE[t] = make_float4(f, e0, e1, W2[t]);
    }
    for (int idx = t; idx < NN; idx += 256)
        sLoc[idx] = ((const float2*)loc)[idx];

    // stage A = K[b] (tf32, padded)
    const float* Kb = &g_K[bN*HH];
    for (int idx = t; idx < NN*16; idx += 256) {
        int row = idx >> 4, f4 = idx & 15;
        float4 v = *(const float4*)&Kb[row*HH + f4*4];
        uint32_t* d = &sA[row*LDA + f4*4];
        d[0] = f2tf32(v.x); d[1] = f2tf32(v.y);
        d[2] = f2tf32(v.z); d[3] = f2tf32(v.w);
    }
    // stage B[m][h] = W1[h,m] * Q[i,h] (tf32, padded)
    const float* Qi = &g_Q[(bN + i)*HH];
    for (int idx = t; idx < HH*MLPD; idx += 256) {
        int h = idx >> 7, m = idx & 127;
        sB[m*LDA + h] = f2tf32(W1[h*MLPD + m] * Qi[h]);
    }
    __syncthreads();

    const int wj  = wid >> 2;      // 0..1  (j half: 256 rows)
    const int wm  = wid & 3;       // 0..3  (m block: 32 cols)
    const int g   = lane >> 2;
    const int tig = lane & 3;

    // hoist B fragments: [kc][ni][2]
    uint32_t Bf[8][4][2];
#pragma unroll
    for (int kc = 0; kc < 8; ++kc)
#pragma unroll
        for (int ni = 0; ni < 4; ++ni) {
            int n = wm*32 + ni*8 + g;
            Bf[kc][ni][0] = sB[n*LDA + kc*8 + tig];
            Bf[kc][ni][1] = sB[n*LDA + kc*8 + tig + 4];
        }

#pragma unroll
    for (int tj = 0; tj < 4; ++tj) {
        const int jb = wj*256 + tj*64;
        float d[4][4][4];
#pragma unroll
        for (int mi = 0; mi < 4; ++mi)
#pragma unroll
            for (int ni = 0; ni < 4; ++ni)
#pragma unroll
                for (int r = 0; r < 4; ++r) d[mi][ni][r] = 0.f;

#pragma unroll
        for (int kc = 0; kc < 8; ++kc) {
            uint32_t Af[4][4];
#pragma unroll
            for (int mi = 0; mi < 4; ++mi) {
                int r0 = jb + mi*16 + g;
                Af[mi][0] = sA[r0*LDA + kc*8 + tig];
                Af[mi][1] = sA[(r0 + 8)*LDA + kc*8 + tig];
                Af[mi][2] = sA[r0*LDA + kc*8 + tig + 4];
                Af[mi][3] = sA[(r0 + 8)*LDA + kc*8 + tig + 4];
            }
#pragma unroll
            for (int mi = 0; mi < 4; ++mi)
#pragma unroll
                for (int ni = 0; ni < 4; ++ni)
                    mma_tf32(d[mi][ni], Af[mi], Bf[kc][ni]);
        }

        // in-register epilogue: relu(S + f + loc_j . e) . W2
#pragma unroll
        for (int mi = 0; mi < 4; ++mi) {
            int j0 = jb + mi*16 + g;
            float2 l0 = sLoc[j0], l1 = sLoc[j0 + 8];
            float p0 = 0.f, p1 = 0.f;
#pragma unroll
            for (int ni = 0; ni < 4; ++ni) {
                int m0 = wm*32 + ni*8 + 2*tig;
                float4 f0 = sFE[m0], f1 = sFE[m0 + 1];
                float v;
                v = d[mi][ni][0] + f0.x + l0.x*f0.y + l0.y*f0.z; p0 = fmaf(fmaxf(v, 0.f), f0.w, p0);
                v = d[mi][ni][1] + f1.x + l0.x*f1.y + l0.y*f1.z; p0 = fmaf(fmaxf(v, 0.f), f1.w, p0);
                v = d[mi][ni][2] + f0.x + l1.x*f0.y + l1.y*f0.z; p1 = fmaf(fmaxf(v, 0.f), f0.w, p1);
                v = d[mi][ni][3] + f1.x + l1.x*f1.y + l1.y*f1.z; p1 = fmaf(fmaxf(v, 0.f), f1.w, p1);
            }
            p0 += __shfl_xor_sync(0xffffffffu, p0, 1);
            p0 += __shfl_xor_sync(0xffffffffu, p0, 2);
            p1 += __shfl_xor_sync(0xffffffffu, p1, 1);
            p1 += __shfl_xor_sync(0xffffffffu, p1, 2);
            if (tig == 0) {
                sSc4[wm*NN + j0]     = p0;
                sSc4[wm*NN + j0 + 8] = p1;
            }
        }
    }
    __syncthreads();

    // ---- softmax over 512 scores ----
    float s0 = sSc4[0*NN + t] + sSc4[1*NN + t] + sSc4[2*NN + t] + sSc4[3*NN + t];
    int t2 = t + 256;
    float s1 = sSc4[0*NN + t2] + sSc4[1*NN + t2] + sSc4[2*NN + t2] + sSc4[3*NN + t2];
    sRed[t] = fmaxf(s0, s1);
    __syncthreads();
#pragma unroll
    for (int s = 128; s > 0; s >>= 1) {
        if (t < s) sRed[t] = fmaxf(sRed[t], sRed[t + s]);
        __syncthreads();
    }
    float rmax = sRed[0];
    __syncthreads();
    float e0 = __expf(s0 - rmax);
    float e1v = __expf(s1 - rmax);
    sSc4[t] = e0;
    sSc4[t + 256] = e1v;
    sRed[t] = e0 + e1v;
    __syncthreads();
#pragma unroll
    for (int s = 128; s > 0; s >>= 1) {
        if (t < s) sRed[t] += sRed[t + s];
        __syncthreads();
    }
    float inv = 1.f / sRed[0];

    // ---- out = attn @ V ----
    {
        int q = t >> 6, h = t & 63;
        const float* Vb = &g_V[bN*HH];
        float a = 0.f;
#pragma unroll 4
        for (int jj = 0; jj < 128; ++jj) {
            int j = q*128 + jj;
            a = fmaf(sSc4[j], Vb[j*HH + h], a);
        }
        sPart[q*HH + h] = a;
    }
    __syncthreads();
    if (t < HH) {
        float o = (sPart[0*HH + t] + sPart[1*HH + t] + sPart[2*HH + t] + sPart[3*HH + t]) * inv;
        out[(bN + i)*HH + t] = o;
    }
}

// ---------------------------------------------------------------------------
extern "C" void kernel_launch(void* const* d_in, const int* in_sizes, int n_in,
                              void* d_out, int out_size) {
    const float* features = (const float*)d_in[0];
    const float* wind     = (const float*)d_in[1];
    const float* loc      = (const float*)d_in[2];
    const float* Wq       = (const float*)d_in[3];
    const float* bq       = (const float*)d_in[4];
    const float* Wk       = (const float*)d_in[5];
    const float* bk       = (const float*)d_in[6];
    const float* Wv       = (const float*)d_in[7];
    const float* bv       = (const float*)d_in[8];
    const float* Wd       = (const float*)d_in[9];
    const float* bd       = (const float*)d_in[10];
    const float* W1       = (const float*)d_in[11];
    const float* b1       = (const float*)d_in[12];
    const float* W2       = (const float*)d_in[13];
    // d_in[14] = b2: softmax-invariant -> dropped.
    (void)in_sizes; (void)n_in; (void)out_size;

    cudaFuncSetAttribute(qkv_kernel, cudaFuncAttributeMaxDynamicSharedMemorySize, QKV_SMEM);
    cudaFuncSetAttribute(attn_kernel, cudaFuncAttributeMaxDynamicSharedMemorySize, SM_TOTAL);

    qkv_kernel<<<BB*NN/QKV_ROWS, 256, QKV_SMEM>>>(features, Wq, bq, Wk, bk, Wv, bv);
    dirfold_kernel<<<1, MLPD>>>(Wd, bd, W1, b1);
    attn_kernel<<<BB*NN, 256, SM_TOTAL>>>(wind, loc, W1, W2, (float*)d_out);
}

// round 4
// speedup vs baseline: 5.8191x; 1.4860x over previous
#include <cuda_runtime.h>
#include <cstdint>

#define BB 4
#define NN 512
#define HH 64
#define DIRD 64
#define MLPD 128

// Scratch (allocation-free rule: __device__ globals)
__device__ float g_Q[BB*NN*HH];
__device__ float g_K[BB*NN*HH];
__device__ float g_V[BB*NN*HH];
__device__ float g_E[4*MLPD];
__device__ float g_c0[MLPD];
__device__ float g_S[BB*NN*NN];   // raw scores, 4 MB

// ---------------------------------------------------------------------------
__device__ __forceinline__ uint32_t f2tf32(float f) {
    uint32_t u;
    asm("cvt.rna.tf32.f32 %0, %1;" : "=r"(u) : "f"(f));
    return u;
}
__device__ __forceinline__ void mma_tf32(float d[4], const uint32_t a[4], const uint32_t b[2]) {
    asm volatile("mma.sync.aligned.m16n8k8.row.col.f32.tf32.tf32.f32 "
                 "{%0,%1,%2,%3}, {%4,%5,%6,%7}, {%8,%9}, {%0,%1,%2,%3};"
                 : "+f"(d[0]), "+f"(d[1]), "+f"(d[2]), "+f"(d[3])
                 : "r"(a[0]), "r"(a[1]), "r"(a[2]), "r"(a[3]),
                   "r"(b[0]), "r"(b[1]));
}

// ---------------------------------------------------------------------------
// Kernel 1: Q/K/V projections. 16 rows per block, W staged in smem.
// ---------------------------------------------------------------------------
#define QKV_ROWS 16
#define QKV_SMEM (3*HH*HH*4 + QKV_ROWS*HH*4)
__global__ void __launch_bounds__(256)
qkv_kernel(const float* __restrict__ feat,
           const float* __restrict__ Wq, const float* __restrict__ bq,
           const float* __restrict__ Wk, const float* __restrict__ bk,
           const float* __restrict__ Wv, const float* __restrict__ bv) {
    extern __shared__ float qs[];
    float* sWq = qs;
    float* sWk = qs + HH*HH;
    float* sWv = qs + 2*HH*HH;
    float* sF  = qs + 3*HH*HH;
    const int t = threadIdx.x;
    const int row0 = blockIdx.x * QKV_ROWS;

    for (int idx = t; idx < HH*HH; idx += 256) {
        sWq[idx] = Wq[idx];
        sWk[idx] = Wk[idx];
        sWv[idx] = Wv[idx];
    }
    for (int idx = t; idx < QKV_ROWS*HH; idx += 256)
        sF[idx] = feat[row0*HH + idx];
    __syncthreads();

    const int h = t & 63;
    const int rg = t >> 6;
    float aq[4], ak[4], av[4];
    float vbq = bq[h], vbk = bk[h], vbv = bv[h];
#pragma unroll
    for (int r = 0; r < 4; ++r) { aq[r] = vbq; ak[r] = vbk; av[r] = vbv; }
#pragma unroll 8
    for (int k = 0; k < HH; ++k) {
        float wq = sWq[k*HH + h], wk = sWk[k*HH + h], wv = sWv[k*HH + h];
#pragma unroll
        for (int r = 0; r < 4; ++r) {
            float f = sF[(rg*4 + r)*HH + k];
            aq[r] = fmaf(f, wq, aq[r]);
            ak[r] = fmaf(f, wk, ak[r]);
            av[r] = fmaf(f, wv, av[r]);
        }
    }
#pragma unroll
    for (int r = 0; r < 4; ++r) {
        int row = row0 + rg*4 + r;
        g_Q[row*HH + h] = aq[r];
        g_K[row*HH + h] = ak[r];
        g_V[row*HH + h] = av[r];
    }
}

// ---------------------------------------------------------------------------
// Kernel 2: fold direction branch. E = Wd @ W1[64:], c0 = b1 + bd @ W1[64:]
// ---------------------------------------------------------------------------
__global__ void dirfold_kernel(const float* __restrict__ Wd, const float* __restrict__ bd,
                               const float* __restrict__ W1, const float* __restrict__ b1) {
    int m = threadIdx.x;
    float e0 = 0.f, e1 = 0.f, e2 = 0.f, e3 = 0.f, c = b1[m];
#pragma unroll 8
    for (int d = 0; d < DIRD; ++d) {
        float w = W1[(HH + d)*MLPD + m];
        e0 = fmaf(Wd[0*DIRD + d], w, e0);
        e1 = fmaf(Wd[1*DIRD + d], w, e1);
        e2 = fmaf(Wd[2*DIRD + d], w, e2);
        e3 = fmaf(Wd[3*DIRD + d], w, e3);
        c  = fmaf(bd[d],          w, c);
    }
    g_E[0*MLPD + m] = e0;
    g_E[1*MLPD + m] = e1;
    g_E[2*MLPD + m] = e2;
    g_E[3*MLPD + m] = e3;
    g_c0[m] = c;
}

// ---------------------------------------------------------------------------
// Kernel 3: scores. Per (b,i): tf32 mma GEMM in 2 j-passes of 256 rows,
// half-size A tile so 2 CTAs fit per SM. Writes raw scores to g_S.
// ---------------------------------------------------------------------------
#define LDA 68
#define SA_OFF   0                  // 256*68*4 = 69632
#define SB_OFF   69632              // 128*68*4 = 34816 -> 104448
#define FE_OFF   104448             // 128*16   = 2048  -> 106496
#define SP_OFF   106496             // 4*256*4  = 4096  -> 110592
#define SQ_OFF   110592             // 64*4     = 256   -> 110848
#define SC_TOTAL 110848

__global__ void __launch_bounds__(256, 2)
scores_kernel(const float* __restrict__ wind, const float* __restrict__ loc,
              const float* __restrict__ W1, const float* __restrict__ W2) {
    extern __shared__ __align__(16) char sm[];
    uint32_t* sA  = (uint32_t*)(sm + SA_OFF);
    uint32_t* sB  = (uint32_t*)(sm + SB_OFF);
    float4*   sFE = (float4*)(sm + FE_OFF);
    float*    sP  = (float*)(sm + SP_OFF);
    float*    sQ  = (float*)(sm + SQ_OFF);

    const int t    = threadIdx.x;
    const int wid  = t >> 5;
    const int lane = t & 31;
    const int blk  = blockIdx.x;
    const int b    = blk >> 9;
    const int i    = blk & (NN - 1);
    const int bN   = b * NN;

    // per-i epilogue constants
    if (t < MLPD) {
        float li0 = loc[i*2 + 0], li1 = loc[i*2 + 1];
        float w0  = wind[(bN + i)*2 + 0], w1v = wind[(bN + i)*2 + 1];
        float e0 = g_E[t], e1 = g_E[MLPD + t], e2 = g_E[2*MLPD + t], e3 = g_E[3*MLPD + t];
        float f  = g_c0[t] - li0*e0 - li1*e1 + w0*e2 + w1v*e3;
        sFE[t] = make_float4(f, e0, e1, W2[t]);
    }
    if (t < HH) sQ[t] = g_Q[(bN + i)*HH + t];
    __syncthreads();

    // stage B[m][h] = W1[h,m] * Q[i,h]  (tf32, padded)
    for (int idx = t; idx < HH*MLPD; idx += 256) {
        int h = idx >> 7, m = idx & 127;
        sB[m*LDA + h] = f2tf32(W1[h*MLPD + m] * sQ[h]);
    }

    const int wj  = wid >> 2;      // 0..1  (j 128-row half of the pass)
    const int wm  = wid & 3;       // 0..3  (m block of 32)
    const int g   = lane >> 2;
    const int tig = lane & 3;
    const float2* loc2 = (const float2*)loc;

#pragma unroll
    for (int p = 0; p < 2; ++p) {
        // stage A = K[b] rows [p*256, p*256+256)
        const float* Kb = &g_K[(bN + p*256)*HH];
        for (int idx = t; idx < 256*16; idx += 256) {
            int row = idx >> 4, f4 = idx & 15;
            float4 v = *(const float4*)&Kb[row*HH + f4*4];
            uint32_t* d = &sA[row*LDA + f4*4];
            d[0] = f2tf32(v.x); d[1] = f2tf32(v.y);
            d[2] = f2tf32(v.z); d[3] = f2tf32(v.w);
        }
        __syncthreads();   // A ready; B ready (p=0); prior pass fully drained

#pragma unroll
        for (int tj = 0; tj < 2; ++tj) {
#pragma unroll
            for (int mh = 0; mh < 2; ++mh) {
                const int rowb = wj*128 + tj*64 + mh*32;
                float d[2][4][4];
#pragma unroll
                for (int mi = 0; mi < 2; ++mi)
#pragma unroll
                    for (int ni = 0; ni < 4; ++ni)
#pragma unroll
                        for (int r = 0; r < 4; ++r) d[mi][ni][r] = 0.f;

#pragma unroll
                for (int kc = 0; kc < 8; ++kc) {
                    uint32_t Af[2][4];
#pragma unroll
                    for (int mi = 0; mi < 2; ++mi) {
                        int r0 = rowb + mi*16 + g;
                        Af[mi][0] = sA[r0*LDA + kc*8 + tig];
                        Af[mi][1] = sA[(r0 + 8)*LDA + kc*8 + tig];
                        Af[mi][2] = sA[r0*LDA + kc*8 + tig + 4];
                        Af[mi][3] = sA[(r0 + 8)*LDA + kc*8 + tig + 4];
                    }
                    uint32_t Bf[4][2];
#pragma unroll
                    for (int ni = 0; ni < 4; ++ni) {
                        int n = wm*32 + ni*8 + g;
                        Bf[ni][0] = sB[n*LDA + kc*8 + tig];
                        Bf[ni][1] = sB[n*LDA + kc*8 + tig + 4];
                    }
#pragma unroll
                    for (int mi = 0; mi < 2; ++mi)
#pragma unroll
                        for (int ni = 0; ni < 4; ++ni)
                            mma_tf32(d[mi][ni], Af[mi], Bf[ni]);
                }

                // in-register epilogue: relu(S + f + loc_j . e) . W2
#pragma unroll
                for (int mi = 0; mi < 2; ++mi) {
                    int jl = rowb + mi*16 + g;
                    int jg = p*256 + jl;
                    float2 l0 = __ldg(&loc2[jg]);
                    float2 l1 = __ldg(&loc2[jg + 8]);
                    float p0 = 0.f, p1 = 0.f;
#pragma unroll
                    for (int ni = 0; ni < 4; ++ni) {
                        int m0 = wm*32 + ni*8 + 2*tig;
                        float4 f0 = sFE[m0], f1 = sFE[m0 + 1];
                        float v;
                        v = d[mi][ni][0] + f0.x + l0.x*f0.y + l0.y*f0.z; p0 = fmaf(fmaxf(v, 0.f), f0.w, p0);
                        v = d[mi][ni][1] + f1.x + l0.x*f1.y + l0.y*f1.z; p0 = fmaf(fmaxf(v, 0.f), f1.w, p0);
                        v = d[mi][ni][2] + f0.x + l1.x*f0.y + l1.y*f0.z; p1 = fmaf(fmaxf(v, 0.f), f0.w, p1);
                        v = d[mi][ni][3] + f1.x + l1.x*f1.y + l1.y*f1.z; p1 = fmaf(fmaxf(v, 0.f), f1.w, p1);
                    }
                    p0 += __shfl_xor_sync(0xffffffffu, p0, 1);
                    p0 += __shfl_xor_sync(0xffffffffu, p0, 2);
                    p1 += __shfl_xor_sync(0xffffffffu, p1, 1);
                    p1 += __shfl_xor_sync(0xffffffffu, p1, 2);
                    if (tig == 0) {
                        sP[wm*256 + jl]     = p0;
                        sP[wm*256 + jl + 8] = p1;
                    }
                }
            }
        }
        __syncthreads();
        // combine 4 m-block partials, write raw scores
        float s = sP[t] + sP[256 + t] + sP[512 + t] + sP[768 + t];
        g_S[(size_t)blk*NN + p*256 + t] = s;
    }
}

// ---------------------------------------------------------------------------
// Kernel 4: softmax over j + out = attn @ V.  One block per (b,i), tiny smem.
// ---------------------------------------------------------------------------
__global__ void __launch_bounds__(256)
smax_av_kernel(float* __restrict__ out) {
    __shared__ float sS[NN];
    __shared__ float sRm[8], sRs[8];
    __shared__ float sPart[4*HH];

    const int t    = threadIdx.x;
    const int wid  = t >> 5;
    const int lane = t & 31;
    const int blk  = blockIdx.x;
    const int b    = blk >> 9;
    const int bN   = b * NN;
    const size_t base = (size_t)blk * NN;

    float s0 = g_S[base + t], s1 = g_S[base + 256 + t];
    float m = fmaxf(s0, s1);
#pragma unroll
    for (int o = 16; o > 0; o >>= 1) m = fmaxf(m, __shfl_xor_sync(0xffffffffu, m, o));
    if (lane == 0) sRm[wid] = m;
    __syncthreads();
    if (t < 8) {
        float v = sRm[t];
#pragma unroll
        for (int o = 4; o > 0; o >>= 1) v = fmaxf(v, __shfl_xor_sync(0xffu, v, o));
        if (t == 0) sRm[0] = v;
    }
    __syncthreads();
    float rmax = sRm[0];

    float e0 = __expf(s0 - rmax);
    float e1 = __expf(s1 - rmax);
    sS[t] = e0;
    sS[t + 256] = e1;
    float sum = e0 + e1;
#pragma unroll
    for (int o = 16; o > 0; o >>= 1) sum += __shfl_xor_sync(0xffffffffu, sum, o);
    if (lane == 0) sRs[wid] = sum;
    __syncthreads();
    if (t < 8) {
        float v = sRs[t];
#pragma unroll
        for (int o = 4; o > 0; o >>= 1) v += __shfl_xor_sync(0xffu, v, o);
        if (t == 0) sRs[0] = v;
    }
    __syncthreads();
    float inv = 1.f / sRs[0];

    // attn @ V : 4 j-quarters x 64 h
    {
        int q = t >> 6, h = t & 63;
        const float* Vb = &g_V[bN*HH];
        float a = 0.f;
#pragma unroll 4
        for (int jj = 0; jj < 128; ++jj) {
            int j = q*128 + jj;
            a = fmaf(sS[j], __ldg(&Vb[j*HH + h]), a);
        }
        sPart[q*HH + h] = a;
    }
    __syncthreads();
    if (t < HH) {
        int i = blk & (NN - 1);
        float o = (sPart[t] + sPart[HH + t] + sPart[2*HH + t] + sPart[3*HH + t]) * inv;
        out[(bN + i)*HH + t] = o;
    }
}

// ---------------------------------------------------------------------------
extern "C" void kernel_launch(void* const* d_in, const int* in_sizes, int n_in,
                              void* d_out, int out_size) {
    const float* features = (const float*)d_in[0];
    const float* wind     = (const float*)d_in[1];
    const float* loc      = (const float*)d_in[2];
    const float* Wq       = (const float*)d_in[3];
    const float* bq       = (const float*)d_in[4];
    const float* Wk       = (const float*)d_in[5];
    const float* bk       = (const float*)d_in[6];
    const float* Wv       = (const float*)d_in[7];
    const float* bv       = (const float*)d_in[8];
    const float* Wd       = (const float*)d_in[9];
    const float* bd       = (const float*)d_in[10];
    const float* W1       = (const float*)d_in[11];
    const float* b1       = (const float*)d_in[12];
    const float* W2       = (const float*)d_in[13];
    // d_in[14] = b2: softmax-invariant -> dropped.
    (void)in_sizes; (void)n_in; (void)out_size;

    cudaFuncSetAttribute(qkv_kernel, cudaFuncAttributeMaxDynamicSharedMemorySize, QKV_SMEM);
    cudaFuncSetAttribute(scores_kernel, cudaFuncAttributeMaxDynamicSharedMemorySize, SC_TOTAL);

    qkv_kernel<<<BB*NN/QKV_ROWS, 256, QKV_SMEM>>>(features, Wq, bq, Wk, bk, Wv, bv);
    dirfold_kernel<<<1, MLPD>>>(Wd, bd, W1, b1);
    scores_kernel<<<BB*NN, 256, SC_TOTAL>>>(wind, loc, W1, W2);
    smax_av_kernel<<<BB*NN, 256>>>((float*)d_out);
}

// round 5
// speedup vs baseline: 6.2112x; 1.0674x over previous
#include <cuda_runtime.h>
#include <cstdint>

#define BB 4
#define NN 512
#define HH 64
#define DIRD 64
#define MLPD 128

// Scratch (allocation-free rule: __device__ globals)
__device__ float g_Q[BB*NN*HH];
__device__ float g_K[BB*NN*HH];
__device__ float g_V[BB*NN*HH];
__device__ float g_E[4*MLPD];
__device__ float g_c0[MLPD];
__device__ float g_S[BB*NN*NN];   // raw scores, 4 MB

// ---------------------------------------------------------------------------
__device__ __forceinline__ uint32_t f2tf32(float f) {
    uint32_t u;
    asm("cvt.rna.tf32.f32 %0, %1;" : "=r"(u) : "f"(f));
    return u;
}
__device__ __forceinline__ void mma_tf32(float d[4], const uint32_t a[4], const uint32_t b[2]) {
    asm volatile("mma.sync.aligned.m16n8k8.row.col.f32.tf32.tf32.f32 "
                 "{%0,%1,%2,%3}, {%4,%5,%6,%7}, {%8,%9}, {%0,%1,%2,%3};"
                 : "+f"(d[0]), "+f"(d[1]), "+f"(d[2]), "+f"(d[3])
                 : "r"(a[0]), "r"(a[1]), "r"(a[2]), "r"(a[3]),
                   "r"(b[0]), "r"(b[1]));
}

// ---------------------------------------------------------------------------
// Kernel 1: Q/K/V projections. 8 rows per block (grid 256, 2 CTAs/SM).
// ---------------------------------------------------------------------------
#define QKV_ROWS 8
#define QKV_SMEM (3*HH*HH*4 + QKV_ROWS*HH*4)
__global__ void __launch_bounds__(256, 2)
qkv_kernel(const float* __restrict__ feat,
           const float* __restrict__ Wq, const float* __restrict__ bq,
           const float* __restrict__ Wk, const float* __restrict__ bk,
           const float* __restrict__ Wv, const float* __restrict__ bv) {
    extern __shared__ float qs[];
    float* sWq = qs;
    float* sWk = qs + HH*HH;
    float* sWv = qs + 2*HH*HH;
    float* sF  = qs + 3*HH*HH;
    const int t = threadIdx.x;
    const int row0 = blockIdx.x * QKV_ROWS;

    for (int idx = t; idx < HH*HH; idx += 256) {
        sWq[idx] = Wq[idx];
        sWk[idx] = Wk[idx];
        sWv[idx] = Wv[idx];
    }
    for (int idx = t; idx < QKV_ROWS*HH; idx += 256)
        sF[idx] = feat[row0*HH + idx];
    __syncthreads();

    const int h = t & 63;
    const int rg = t >> 6;               // 4 groups x 2 rows
    float aq[2], ak[2], av[2];
    float vbq = bq[h], vbk = bk[h], vbv = bv[h];
#pragma unroll
    for (int r = 0; r < 2; ++r) { aq[r] = vbq; ak[r] = vbk; av[r] = vbv; }
#pragma unroll 8
    for (int k = 0; k < HH; ++k) {
        float wq = sWq[k*HH + h], wk = sWk[k*HH + h], wv = sWv[k*HH + h];
#pragma unroll
        for (int r = 0; r < 2; ++r) {
            float f = sF[(rg*2 + r)*HH + k];
            aq[r] = fmaf(f, wq, aq[r]);
            ak[r] = fmaf(f, wk, ak[r]);
            av[r] = fmaf(f, wv, av[r]);
        }
    }
#pragma unroll
    for (int r = 0; r < 2; ++r) {
        int row = row0 + rg*2 + r;
        g_Q[row*HH + h] = aq[r];
        g_K[row*HH + h] = ak[r];
        g_V[row*HH + h] = av[r];
    }
}

// ---------------------------------------------------------------------------
// Kernel 2: fold direction branch. E = Wd @ W1[64:], c0 = b1 + bd @ W1[64:]
// ---------------------------------------------------------------------------
__global__ void dirfold_kernel(const float* __restrict__ Wd, const float* __restrict__ bd,
                               const float* __restrict__ W1, const float* __restrict__ b1) {
    int m = threadIdx.x;
    float e0 = 0.f, e1 = 0.f, e2 = 0.f, e3 = 0.f, c = b1[m];
#pragma unroll 8
    for (int d = 0; d < DIRD; ++d) {
        float w = W1[(HH + d)*MLPD + m];
        e0 = fmaf(Wd[0*DIRD + d], w, e0);
        e1 = fmaf(Wd[1*DIRD + d], w, e1);
        e2 = fmaf(Wd[2*DIRD + d], w, e2);
        e3 = fmaf(Wd[3*DIRD + d], w, e3);
        c  = fmaf(bd[d],          w, c);
    }
    g_E[0*MLPD + m] = e0;
    g_E[1*MLPD + m] = e1;
    g_E[2*MLPD + m] = e2;
    g_E[3*MLPD + m] = e3;
    g_c0[m] = c;
}

// ---------------------------------------------------------------------------
// Kernel 3: scores. Per (b,i): tf32 mma GEMM, 2 j-passes of 256 rows,
// warp tile 64 j-rows x 32 m. 2 CTAs/SM. Writes raw scores to g_S.
// ---------------------------------------------------------------------------
#define LDA 68
#define SA_OFF   0                  // 256*68*4 = 69632
#define SB_OFF   69632              // 128*68*4 = 34816 -> 104448
#define FE_OFF   104448             // 128*16   = 2048  -> 106496
#define SP_OFF   106496             // 4*256*4  = 4096  -> 110592
#define SQ_OFF   110592             // 64*4     = 256   -> 110848
#define SC_TOTAL 110848

__global__ void __launch_bounds__(256, 2)
scores_kernel(const float* __restrict__ wind, const float* __restrict__ loc,
              const float* __restrict__ W1, const float* __restrict__ W2) {
    extern __shared__ __align__(16) char sm[];
    uint32_t* sA  = (uint32_t*)(sm + SA_OFF);
    uint32_t* sB  = (uint32_t*)(sm + SB_OFF);
    float4*   sFE = (float4*)(sm + FE_OFF);
    float*    sP  = (float*)(sm + SP_OFF);
    float*    sQ  = (float*)(sm + SQ_OFF);

    const int t    = threadIdx.x;
    const int wid  = t >> 5;
    const int lane = t & 31;
    const int blk  = blockIdx.x;
    const int b    = blk >> 9;
    const int i    = blk & (NN - 1);
    const int bN   = b * NN;

    // per-i epilogue constants
    if (t < MLPD) {
        float li0 = loc[i*2 + 0], li1 = loc[i*2 + 1];
        float w0  = wind[(bN + i)*2 + 0], w1v = wind[(bN + i)*2 + 1];
        float e0 = g_E[t], e1 = g_E[MLPD + t], e2 = g_E[2*MLPD + t], e3 = g_E[3*MLPD + t];
        float f  = g_c0[t] - li0*e0 - li1*e1 + w0*e2 + w1v*e3;
        sFE[t] = make_float4(f, e0, e1, W2[t]);
    }
    if (t < HH) sQ[t] = g_Q[(bN + i)*HH + t];
    __syncthreads();

    // stage B[m][h] = W1[h,m] * Q[i,h]  (tf32, padded)
    for (int idx = t; idx < HH*MLPD; idx += 256) {
        int h = idx >> 7, m = idx & 127;
        sB[m*LDA + h] = f2tf32(W1[h*MLPD + m] * sQ[h]);
    }

    const int wj  = wid >> 2;      // 0..1  (j 128-row half of the pass)
    const int wm  = wid & 3;       // 0..3  (m block of 32)
    const int g   = lane >> 2;
    const int tig = lane & 3;
    const float2* loc2 = (const float2*)loc;

#pragma unroll
    for (int p = 0; p < 2; ++p) {
        // stage A = K[b] rows [p*256, p*256+256)
        const float* Kb = &g_K[(bN + p*256)*HH];
        for (int idx = t; idx < 256*16; idx += 256) {
            int row = idx >> 4, f4 = idx & 15;
            float4 v = *(const float4*)&Kb[row*HH + f4*4];
            uint32_t* d = &sA[row*LDA + f4*4];
            d[0] = f2tf32(v.x); d[1] = f2tf32(v.y);
            d[2] = f2tf32(v.z); d[3] = f2tf32(v.w);
        }
        __syncthreads();   // A ready; B ready (p=0); prior pass fully drained

#pragma unroll
        for (int tj = 0; tj < 2; ++tj) {
            const int rowb = wj*128 + tj*64;
            float d[4][4][4];
#pragma unroll
            for (int mi = 0; mi < 4; ++mi)
#pragma unroll
                for (int ni = 0; ni < 4; ++ni)
#pragma unroll
                    for (int r = 0; r < 4; ++r) d[mi][ni][r] = 0.f;

#pragma unroll
            for (int kc = 0; kc < 8; ++kc) {
                uint32_t Af[4][4];
#pragma unroll
                for (int mi = 0; mi < 4; ++mi) {
                    int r0 = rowb + mi*16 + g;
                    Af[mi][0] = sA[r0*LDA + kc*8 + tig];
                    Af[mi][1] = sA[(r0 + 8)*LDA + kc*8 + tig];
                    Af[mi][2] = sA[r0*LDA + kc*8 + tig + 4];
                    Af[mi][3] = sA[(r0 + 8)*LDA + kc*8 + tig + 4];
                }
                uint32_t Bf[4][2];
#pragma unroll
                for (int ni = 0; ni < 4; ++ni) {
                    int n = wm*32 + ni*8 + g;
                    Bf[ni][0] = sB[n*LDA + kc*8 + tig];
                    Bf[ni][1] = sB[n*LDA + kc*8 + tig + 4];
                }
#pragma unroll
                for (int mi = 0; mi < 4; ++mi)
#pragma unroll
                    for (int ni = 0; ni < 4; ++ni)
                        mma_tf32(d[mi][ni], Af[mi], Bf[ni]);
            }

            // in-register epilogue: relu(S + f + loc_j . e) . W2
#pragma unroll
            for (int mi = 0; mi < 4; ++mi) {
                int jl = rowb + mi*16 + g;
                int jg = p*256 + jl;
                float2 l0 = __ldg(&loc2[jg]);
                float2 l1 = __ldg(&loc2[jg + 8]);
                float p0 = 0.f, p1 = 0.f;
#pragma unroll
                for (int ni = 0; ni < 4; ++ni) {
                    int m0 = wm*32 + ni*8 + 2*tig;
                    float4 f0 = sFE[m0], f1 = sFE[m0 + 1];
                    float v;
                    v = d[mi][ni][0] + f0.x + l0.x*f0.y + l0.y*f0.z; p0 = fmaf(fmaxf(v, 0.f), f0.w, p0);
                    v = d[mi][ni][1] + f1.x + l0.x*f1.y + l0.y*f1.z; p0 = fmaf(fmaxf(v, 0.f), f1.w, p0);
                    v = d[mi][ni][2] + f0.x + l1.x*f0.y + l1.y*f0.z; p1 = fmaf(fmaxf(v, 0.f), f0.w, p1);
                    v = d[mi][ni][3] + f1.x + l1.x*f1.y + l1.y*f1.z; p1 = fmaf(fmaxf(v, 0.f), f1.w, p1);
                }
                p0 += __shfl_xor_sync(0xffffffffu, p0, 1);
                p0 += __shfl_xor_sync(0xffffffffu, p0, 2);
                p1 += __shfl_xor_sync(0xffffffffu, p1, 1);
                p1 += __shfl_xor_sync(0xffffffffu, p1, 2);
                if (tig == 0) {
                    sP[wm*256 + jl]     = p0;
                    sP[wm*256 + jl + 8] = p1;
                }
            }
        }
        __syncthreads();
        // combine 4 m-block partials, write raw scores
        float s = sP[t] + sP[256 + t] + sP[512 + t] + sP[768 + t];
        g_S[(size_t)blk*NN + p*256 + t] = s;
    }
}

// ---------------------------------------------------------------------------
// Kernel 4: batched softmax + attn@V. 16 i's per block (grid 128).
// Scores tile (16x512) + V j-tiles (128x64) in smem -> V read once per block.
// ---------------------------------------------------------------------------
#define IB 16
#define AV_SMEM (IB*NN*4 + 128*HH*4 + IB*4)   // 32768 + 32768 + 64 = 65600
__global__ void __launch_bounds__(256)
smax_av_kernel(float* __restrict__ out) {
    extern __shared__ __align__(16) float avs[];
    float* sS   = avs;               // [IB][NN]
    float* sV   = avs + IB*NN;       // [128][HH]
    float* sInv = avs + IB*NN + 128*HH;  // [IB]

    const int t    = threadIdx.x;
    const int wid  = t >> 5;
    const int lane = t & 31;
    const int b    = blockIdx.x >> 5;        // 32 i-groups per batch
    const int i0   = (blockIdx.x & 31) * IB;
    const int bN   = b * NN;

    // load 16 rows of raw scores (float4, coalesced)
    {
        const float4* src = (const float4*)&g_S[((size_t)bN + i0) * NN];
        float4* dst = (float4*)sS;
        for (int idx = t; idx < IB*NN/4; idx += 256) dst[idx] = src[idx];
    }
    __syncthreads();

    // per-row softmax: each warp owns 2 rows entirely (no cross-warp reduce)
#pragma unroll
    for (int rr = 0; rr < 2; ++rr) {
        int row = wid*2 + rr;
        float* r = &sS[row*NN];
        float m = -1e30f;
#pragma unroll
        for (int c = 0; c < NN/32; ++c) m = fmaxf(m, r[c*32 + lane]);
#pragma unroll
        for (int o = 16; o > 0; o >>= 1) m = fmaxf(m, __shfl_xor_sync(0xffffffffu, m, o));
        float sum = 0.f;
#pragma unroll
        for (int c = 0; c < NN/32; ++c) {
            float e = __expf(r[c*32 + lane] - m);
            r[c*32 + lane] = e;
            sum += e;
        }
#pragma unroll
        for (int o = 16; o > 0; o >>= 1) sum += __shfl_xor_sync(0xffffffffu, sum, o);
        if (lane == 0) sInv[row] = 1.f / sum;
    }

    // AV: thread owns (i, h-quad); V staged in 128-row j-tiles
    const int ti  = t >> 4;     // 0..15
    const int th4 = t & 15;     // 0..15 (4 h each)
    float4 acc = make_float4(0.f, 0.f, 0.f, 0.f);

#pragma unroll
    for (int jt = 0; jt < 4; ++jt) {
        __syncthreads();
        {
            const float4* src = (const float4*)&g_V[(bN + jt*128)*HH];
            float4* dst = (float4*)sV;
            for (int idx = t; idx < 128*HH/4; idx += 256) dst[idx] = src[idx];
        }
        __syncthreads();
        const float* Prow = &sS[ti*NN + jt*128];
        const float4* V4  = (const float4*)sV;
#pragma unroll 4
        for (int j = 0; j < 128; ++j) {
            float p = Prow[j];
            float4 v = V4[j*16 + th4];
            acc.x = fmaf(p, v.x, acc.x);
            acc.y = fmaf(p, v.y, acc.y);
            acc.z = fmaf(p, v.z, acc.z);
            acc.w = fmaf(p, v.w, acc.w);
        }
    }

    float inv = sInv[ti];
    acc.x *= inv; acc.y *= inv; acc.z *= inv; acc.w *= inv;
    ((float4*)&out[(bN + i0 + ti)*HH])[th4] = acc;
}

// ---------------------------------------------------------------------------
extern "C" void kernel_launch(void* const* d_in, const int* in_sizes, int n_in,
                              void* d_out, int out_size) {
    const float* features = (const float*)d_in[0];
    const float* wind     = (const float*)d_in[1];
    const float* loc      = (const float*)d_in[2];
    const float* Wq       = (const float*)d_in[3];
    const float* bq       = (const float*)d_in[4];
    const float* Wk       = (const float*)d_in[5];
    const float* bk       = (const float*)d_in[6];
    const float* Wv       = (const float*)d_in[7];
    const float* bv       = (const float*)d_in[8];
    const float* Wd       = (const float*)d_in[9];
    const float* bd       = (const float*)d_in[10];
    const float* W1       = (const float*)d_in[11];
    const float* b1       = (const float*)d_in[12];
    const float* W2       = (const float*)d_in[13];
    // d_in[14] = b2: softmax-invariant -> dropped.
    (void)in_sizes; (void)n_in; (void)out_size;

    cudaFuncSetAttribute(qkv_kernel, cudaFuncAttributeMaxDynamicSharedMemorySize, QKV_SMEM);
    cudaFuncSetAttribute(scores_kernel, cudaFuncAttributeMaxDynamicSharedMemorySize, SC_TOTAL);
    cudaFuncSetAttribute(smax_av_kernel, cudaFuncAttributeMaxDynamicSharedMemorySize, AV_SMEM);

    qkv_kernel<<<BB*NN/QKV_ROWS, 256, QKV_SMEM>>>(features, Wq, bq, Wk, bk, Wv, bv);
    dirfold_kernel<<<1, MLPD>>>(Wd, bd, W1, b1);
    scores_kernel<<<BB*NN, 256, SC_TOTAL>>>(wind, loc, W1, W2);
    smax_av_kernel<<<BB*NN/IB, 256, AV_SMEM>>>((float*)d_out);
}

// round 6
// speedup vs baseline: 8.0561x; 1.2970x over previous
#include <cuda_runtime.h>
#include <cuda_fp16.h>
#include <cstdint>

#define BB 4
#define NN 512
#define HH 64
#define DIRD 64
#define MLPD 128

// Scratch (allocation-free rule: __device__ globals)
__device__ float g_Q[BB*NN*HH];
__device__ float g_K[BB*NN*HH];
__device__ float g_V[BB*NN*HH];
__device__ float g_E[4*MLPD];
__device__ float g_c0[MLPD];
__device__ float g_S[BB*NN*NN];   // raw scores, 4 MB

// ---------------------------------------------------------------------------
__device__ __forceinline__ void mma_f16(float d[4], const uint32_t a[4], const uint32_t b[2]) {
    asm volatile("mma.sync.aligned.m16n8k16.row.col.f32.f16.f16.f32 "
                 "{%0,%1,%2,%3}, {%4,%5,%6,%7}, {%8,%9}, {%0,%1,%2,%3};"
                 : "+f"(d[0]), "+f"(d[1]), "+f"(d[2]), "+f"(d[3])
                 : "r"(a[0]), "r"(a[1]), "r"(a[2]), "r"(a[3]),
                   "r"(b[0]), "r"(b[1]));
}

// ---------------------------------------------------------------------------
// Kernel 1: Q/K/V projections. 8 rows per block (grid 256, 2 CTAs/SM).
// ---------------------------------------------------------------------------
#define QKV_ROWS 8
#define QKV_SMEM (3*HH*HH*4 + QKV_ROWS*HH*4)
__global__ void __launch_bounds__(256, 2)
qkv_kernel(const float* __restrict__ feat,
           const float* __restrict__ Wq, const float* __restrict__ bq,
           const float* __restrict__ Wk, const float* __restrict__ bk,
           const float* __restrict__ Wv, const float* __restrict__ bv) {
    extern __shared__ float qs[];
    float* sWq = qs;
    float* sWk = qs + HH*HH;
    float* sWv = qs + 2*HH*HH;
    float* sF  = qs + 3*HH*HH;
    const int t = threadIdx.x;
    const int row0 = blockIdx.x * QKV_ROWS;

    for (int idx = t; idx < HH*HH; idx += 256) {
        sWq[idx] = Wq[idx];
        sWk[idx] = Wk[idx];
        sWv[idx] = Wv[idx];
    }
    for (int idx = t; idx < QKV_ROWS*HH; idx += 256)
        sF[idx] = feat[row0*HH + idx];
    __syncthreads();

    const int h = t & 63;
    const int rg = t >> 6;               // 4 groups x 2 rows
    float aq[2], ak[2], av[2];
    float vbq = bq[h], vbk = bk[h], vbv = bv[h];
#pragma unroll
    for (int r = 0; r < 2; ++r) { aq[r] = vbq; ak[r] = vbk; av[r] = vbv; }
#pragma unroll 8
    for (int k = 0; k < HH; ++k) {
        float wq = sWq[k*HH + h], wk = sWk[k*HH + h], wv = sWv[k*HH + h];
#pragma unroll
        for (int r = 0; r < 2; ++r) {
            float f = sF[(rg*2 + r)*HH + k];
            aq[r] = fmaf(f, wq, aq[r]);
            ak[r] = fmaf(f, wk, ak[r]);
            av[r] = fmaf(f, wv, av[r]);
        }
    }
#pragma unroll
    for (int r = 0; r < 2; ++r) {
        int row = row0 + rg*2 + r;
        g_Q[row*HH + h] = aq[r];
        g_K[row*HH + h] = ak[r];
        g_V[row*HH + h] = av[r];
    }
}

// ---------------------------------------------------------------------------
// Kernel 2: fold direction branch. E = Wd @ W1[64:], c0 = b1 + bd @ W1[64:]
// ---------------------------------------------------------------------------
__global__ void dirfold_kernel(const float* __restrict__ Wd, const float* __restrict__ bd,
                               const float* __restrict__ W1, const float* __restrict__ b1) {
    int m = threadIdx.x;
    float e0 = 0.f, e1 = 0.f, e2 = 0.f, e3 = 0.f, c = b1[m];
#pragma unroll 8
    for (int d = 0; d < DIRD; ++d) {
        float w = W1[(HH + d)*MLPD + m];
        e0 = fmaf(Wd[0*DIRD + d], w, e0);
        e1 = fmaf(Wd[1*DIRD + d], w, e1);
        e2 = fmaf(Wd[2*DIRD + d], w, e2);
        e3 = fmaf(Wd[3*DIRD + d], w, e3);
        c  = fmaf(bd[d],          w, c);
    }
    g_E[0*MLPD + m] = e0;
    g_E[1*MLPD + m] = e1;
    g_E[2*MLPD + m] = e2;
    g_E[3*MLPD + m] = e3;
    g_c0[m] = c;
}

// ---------------------------------------------------------------------------
// Kernel 3: scores. Per (b,i): fp16 mma (m16n8k16) GEMM, 2 j-passes of 256,
// warp tile 64 j-rows x 32 m. 2 CTAs/SM. Writes raw scores to g_S.
// ---------------------------------------------------------------------------
#define LDH 72                       // padded row stride in halves (144 B)
#define SA_OFF   0                   // 256*72*2 = 36864
#define SB_OFF   36864               // 128*72*2 = 18432 -> 55296
#define FE_OFF   55296               // 128*16   = 2048  -> 57344
#define SP_OFF   57344               // 4*256*4  = 4096  -> 61440
#define SQ_OFF   61440               // 64*4     = 256   -> 61696
#define SC_TOTAL 61696

__global__ void __launch_bounds__(256, 2)
scores_kernel(const float* __restrict__ wind, const float* __restrict__ loc,
              const float* __restrict__ W1, const float* __restrict__ W2) {
    extern __shared__ __align__(16) char sm[];
    __half*  sA  = (__half*)(sm + SA_OFF);
    __half*  sB  = (__half*)(sm + SB_OFF);
    float4*  sFE = (float4*)(sm + FE_OFF);
    float*   sP  = (float*)(sm + SP_OFF);
    float*   sQ  = (float*)(sm + SQ_OFF);

    const int t    = threadIdx.x;
    const int wid  = t >> 5;
    const int lane = t & 31;
    const int blk  = blockIdx.x;
    const int b    = blk >> 9;
    const int i    = blk & (NN - 1);
    const int bN   = b * NN;

    // per-i epilogue constants
    if (t < MLPD) {
        float li0 = loc[i*2 + 0], li1 = loc[i*2 + 1];
        float w0  = wind[(bN + i)*2 + 0], w1v = wind[(bN + i)*2 + 1];
        float e0 = g_E[t], e1 = g_E[MLPD + t], e2 = g_E[2*MLPD + t], e3 = g_E[3*MLPD + t];
        float f  = g_c0[t] - li0*e0 - li1*e1 + w0*e2 + w1v*e3;
        sFE[t] = make_float4(f, e0, e1, W2[t]);
    }
    if (t < HH) sQ[t] = g_Q[(bN + i)*HH + t];
    __syncthreads();

    // stage B[m][h] = f16(W1[h,m] * Q[i,h])
    for (int idx = t; idx < HH*MLPD; idx += 256) {
        int h = idx >> 7, m = idx & 127;
        sB[m*LDH + h] = __float2half_rn(W1[h*MLPD + m] * sQ[h]);
    }

    const int wj  = wid >> 2;      // 0..1  (j 128-row half of the pass)
    const int wm  = wid & 3;       // 0..3  (m block of 32)
    const int g   = lane >> 2;
    const int tig = lane & 3;
    const float2* loc2 = (const float2*)loc;

#pragma unroll
    for (int p = 0; p < 2; ++p) {
        // stage A = f16(K[b] rows [p*256, p*256+256))
        const float* Kb = &g_K[(bN + p*256)*HH];
        for (int idx = t; idx < 256*16; idx += 256) {
            int row = idx >> 4, f4 = idx & 15;
            float4 v = *(const float4*)&Kb[row*HH + f4*4];
            __half2* d = (__half2*)&sA[row*LDH + f4*4];
            d[0] = __floats2half2_rn(v.x, v.y);
            d[1] = __floats2half2_rn(v.z, v.w);
        }
        __syncthreads();   // A ready; B ready (p=0); prior pass fully drained

#pragma unroll
        for (int tj = 0; tj < 2; ++tj) {
            const int rowb = wj*128 + tj*64;
            float d[4][4][4];
#pragma unroll
            for (int mi = 0; mi < 4; ++mi)
#pragma unroll
                for (int ni = 0; ni < 4; ++ni)
#pragma unroll
                    for (int r = 0; r < 4; ++r) d[mi][ni][r] = 0.f;

#pragma unroll
            for (int kc = 0; kc < 4; ++kc) {     // 4 chunks of k=16
                const int k0 = kc*16 + tig*2;
                uint32_t Af[4][4];
#pragma unroll
                for (int mi = 0; mi < 4; ++mi) {
                    int r0 = rowb + mi*16 + g;
                    Af[mi][0] = *(const uint32_t*)&sA[r0*LDH + k0];
                    Af[mi][1] = *(const uint32_t*)&sA[(r0 + 8)*LDH + k0];
                    Af[mi][2] = *(const uint32_t*)&sA[r0*LDH + k0 + 8];
                    Af[mi][3] = *(const uint32_t*)&sA[(r0 + 8)*LDH + k0 + 8];
                }
                uint32_t Bf[4][2];
#pragma unroll
                for (int ni = 0; ni < 4; ++ni) {
                    int n = wm*32 + ni*8 + g;
                    Bf[ni][0] = *(const uint32_t*)&sB[n*LDH + k0];
                    Bf[ni][1] = *(const uint32_t*)&sB[n*LDH + k0 + 8];
                }
#pragma unroll
                for (int mi = 0; mi < 4; ++mi)
#pragma unroll
                    for (int ni = 0; ni < 4; ++ni)
                        mma_f16(d[mi][ni], Af[mi], Bf[ni]);
            }

            // in-register epilogue: relu(S + f + loc_j . e) . W2
#pragma unroll
            for (int mi = 0; mi < 4; ++mi) {
                int jl = rowb + mi*16 + g;
                int jg = p*256 + jl;
                float2 l0 = __ldg(&loc2[jg]);
                float2 l1 = __ldg(&loc2[jg + 8]);
                float p0 = 0.f, p1 = 0.f;
#pragma unroll
                for (int ni = 0; ni < 4; ++ni) {
                    int m0 = wm*32 + ni*8 + 2*tig;
                    float4 f0 = sFE[m0], f1 = sFE[m0 + 1];
                    float v;
                    v = d[mi][ni][0] + f0.x + l0.x*f0.y + l0.y*f0.z; p0 = fmaf(fmaxf(v, 0.f), f0.w, p0);
                    v = d[mi][ni][1] + f1.x + l0.x*f1.y + l0.y*f1.z; p0 = fmaf(fmaxf(v, 0.f), f1.w, p0);
                    v = d[mi][ni][2] + f0.x + l1.x*f0.y + l1.y*f0.z; p1 = fmaf(fmaxf(v, 0.f), f0.w, p1);
                    v = d[mi][ni][3] + f1.x + l1.x*f1.y + l1.y*f1.z; p1 = fmaf(fmaxf(v, 0.f), f1.w, p1);
                }
                p0 += __shfl_xor_sync(0xffffffffu, p0, 1);
                p0 += __shfl_xor_sync(0xffffffffu, p0, 2);
                p1 += __shfl_xor_sync(0xffffffffu, p1, 1);
                p1 += __shfl_xor_sync(0xffffffffu, p1, 2);
                if (tig == 0) {
                    sP[wm*256 + jl]     = p0;
                    sP[wm*256 + jl + 8] = p1;
                }
            }
        }
        __syncthreads();
        // combine 4 m-block partials, write raw scores
        float s = sP[t] + sP[256 + t] + sP[512 + t] + sP[768 + t];
        g_S[(size_t)blk*NN + p*256 + t] = s;
    }
}

// ---------------------------------------------------------------------------
// Kernel 4: batched softmax + attn@V. 16 i's per block (grid 128), 512 thr.
// One warp per softmax row; AV split across j-halves per half-warp.
// ---------------------------------------------------------------------------
#define IB 16
#define AV_SMEM (IB*NN*4 + 128*HH*4 + IB*4)   // 32768 + 32768 + 64 = 65600
__global__ void __launch_bounds__(512)
smax_av_kernel(float* __restrict__ out) {
    extern __shared__ __align__(16) float avs[];
    float* sS   = avs;                   // [IB][NN]
    float* sV   = avs + IB*NN;           // [128][HH]
    float* sInv = avs + IB*NN + 128*HH;  // [IB]

    const int t    = threadIdx.x;
    const int wid  = t >> 5;
    const int lane = t & 31;
    const int b    = blockIdx.x >> 5;        // 32 i-groups per batch
    const int i0   = (blockIdx.x & 31) * IB;
    const int bN   = b * NN;

    // load 16 rows of raw scores (float4, coalesced)
    {
        const float4* src = (const float4*)&g_S[((size_t)bN + i0) * NN];
        float4* dst = (float4*)sS;
        for (int idx = t; idx < IB*NN/4; idx += 512) dst[idx] = src[idx];
    }
    __syncthreads();

    // per-row softmax: warp wid owns row wid
    {
        float* r = &sS[wid*NN];
        float m = -1e30f;
#pragma unroll
        for (int c = 0; c < NN/32; ++c) m = fmaxf(m, r[c*32 + lane]);
#pragma unroll
        for (int o = 16; o > 0; o >>= 1) m = fmaxf(m, __shfl_xor_sync(0xffffffffu, m, o));
        float sum = 0.f;
#pragma unroll
        for (int c = 0; c < NN/32; ++c) {
            float e = __expf(r[c*32 + lane] - m);
            r[c*32 + lane] = e;
            sum += e;
        }
#pragma unroll
        for (int o = 16; o > 0; o >>= 1) sum += __shfl_xor_sync(0xffffffffu, sum, o);
        if (lane == 0) sInv[wid] = 1.f / sum;
    }

    // AV: warp owns i=wid; lane = (jh, h4): jh = lane>>4 covers j-half of tile
    const int h4 = lane & 15;
    const int jh = lane >> 4;
    float4 acc = make_float4(0.f, 0.f, 0.f, 0.f);

#pragma unroll
    for (int jt = 0; jt < 4; ++jt) {
        __syncthreads();
        {
            const float4* src = (const float4*)&g_V[(bN + jt*128)*HH];
            float4* dst = (float4*)sV;
            for (int idx = t; idx < 128*HH/4; idx += 512) dst[idx] = src[idx];
        }
        __syncthreads();
        const float* Prow = &sS[wid*NN + jt*128 + jh*64];
        const float4* V4  = (const float4*)sV;
#pragma unroll 4
        for (int j = 0; j < 64; ++j) {
            float p = Prow[j];
            float4 v = V4[(jh*64 + j)*16 + h4];
            acc.x = fmaf(p, v.x, acc.x);
            acc.y = fmaf(p, v.y, acc.y);
            acc.z = fmaf(p, v.z, acc.z);
            acc.w = fmaf(p, v.w, acc.w);
        }
    }

    // combine the two j-halves (lane ^ 16), then lanes < 16 write
    acc.x += __shfl_xor_sync(0xffffffffu, acc.x, 16);
    acc.y += __shfl_xor_sync(0xffffffffu, acc.y, 16);
    acc.z += __shfl_xor_sync(0xffffffffu, acc.z, 16);
    acc.w += __shfl_xor_sync(0xffffffffu, acc.w, 16);
    if (jh == 0) {
        float inv = sInv[wid];
        acc.x *= inv; acc.y *= inv; acc.z *= inv; acc.w *= inv;
        ((float4*)&out[(bN + i0 + wid)*HH])[h4] = acc;
    }
}

// ---------------------------------------------------------------------------
extern "C" void kernel_launch(void* const* d_in, const int* in_sizes, int n_in,
                              void* d_out, int out_size) {
    const float* features = (const float*)d_in[0];
    const float* wind     = (const float*)d_in[1];
    const float* loc      = (const float*)d_in[2];
    const float* Wq       = (const float*)d_in[3];
    const float* bq       = (const float*)d_in[4];
    const float* Wk       = (const float*)d_in[5];
    const float* bk       = (const float*)d_in[6];
    const float* Wv       = (const float*)d_in[7];
    const float* bv       = (const float*)d_in[8];
    const float* Wd       = (const float*)d_in[9];
    const float* bd       = (const float*)d_in[10];
    const float* W1       = (const float*)d_in[11];
    const float* b1       = (const float*)d_in[12];
    const float* W2       = (const float*)d_in[13];
    // d_in[14] = b2: softmax-invariant -> dropped.
    (void)in_sizes; (void)n_in; (void)out_size;

    cudaFuncSetAttribute(qkv_kernel, cudaFuncAttributeMaxDynamicSharedMemorySize, QKV_SMEM);
    cudaFuncSetAttribute(scores_kernel, cudaFuncAttributeMaxDynamicSharedMemorySize, SC_TOTAL);
    cudaFuncSetAttribute(smax_av_kernel, cudaFuncAttributeMaxDynamicSharedMemorySize, AV_SMEM);

    qkv_kernel<<<BB*NN/QKV_ROWS, 256, QKV_SMEM>>>(features, Wq, bq, Wk, bk, Wv, bv);
    dirfold_kernel<<<1, MLPD>>>(Wd, bd, W1, b1);
    scores_kernel<<<BB*NN, 256, SC_TOTAL>>>(wind, loc, W1, W2);
    smax_av_kernel<<<BB*NN/IB, 512, AV_SMEM>>>((float*)d_out);
}

// round 7
// speedup vs baseline: 9.2043x; 1.1425x over previous
#include <cuda_runtime.h>
#include <cuda_fp16.h>
#include <cstdint>

#define BB 4
#define NN 512
#define HH 64
#define DIRD 64
#define MLPD 128

// Scratch (allocation-free rule: __device__ globals)
__device__ float g_Q[BB*NN*HH];
__device__ __align__(16) __half g_Kh[BB*NN*HH];
__device__ float g_V[BB*NN*HH];
__device__ float g_E[4*MLPD];
__device__ float g_c0[MLPD];
__device__ float g_S[BB*NN*NN];   // raw scores, 4 MB

// ---------------------------------------------------------------------------
__device__ __forceinline__ uint32_t smem_u32(const void* p) {
    uint32_t a;
    asm("{ .reg .u64 t; cvta.to.shared.u64 t, %1; cvt.u32.u64 %0, t; }" : "=r"(a) : "l"(p));
    return a;
}
__device__ __forceinline__ void mma_f16(float d[4], const uint32_t a[4], const uint32_t b[2]) {
    asm volatile("mma.sync.aligned.m16n8k16.row.col.f32.f16.f16.f32 "
                 "{%0,%1,%2,%3}, {%4,%5,%6,%7}, {%8,%9}, {%0,%1,%2,%3};"
                 : "+f"(d[0]), "+f"(d[1]), "+f"(d[2]), "+f"(d[3])
                 : "r"(a[0]), "r"(a[1]), "r"(a[2]), "r"(a[3]),
                   "r"(b[0]), "r"(b[1]));
}
#define CP_A16(dst, src) \
    asm volatile("cp.async.cg.shared.global [%0], [%1], 16;" :: "r"(dst), "l"(src) : "memory")
#define CP_COMMIT() asm volatile("cp.async.commit_group;" ::: "memory")
#define CP_WAIT(n)  asm volatile("cp.async.wait_group %0;" :: "n"(n) : "memory")

// ---------------------------------------------------------------------------
// Kernel 1: Q/K/V projections (K stored fp16). Last block: dirfold.
// ---------------------------------------------------------------------------
#define QKV_ROWS 8
#define QKV_SMEM (3*HH*HH*4 + QKV_ROWS*HH*4)
__global__ void __launch_bounds__(256, 2)
qkv_kernel(const float* __restrict__ feat,
           const float* __restrict__ Wq, const float* __restrict__ bq,
           const float* __restrict__ Wk, const float* __restrict__ bk,
           const float* __restrict__ Wv, const float* __restrict__ bv,
           const float* __restrict__ Wd, const float* __restrict__ bd,
           const float* __restrict__ W1, const float* __restrict__ b1) {
    const int t = threadIdx.x;

    if (blockIdx.x == BB*NN/QKV_ROWS) {
        // ---- dirfold: E = Wd @ W1[64:], c0 = b1 + bd @ W1[64:]
        if (t < MLPD) {
            int m = t;
            float e0 = 0.f, e1 = 0.f, e2 = 0.f, e3 = 0.f, c = b1[m];
#pragma unroll 8
            for (int d = 0; d < DIRD; ++d) {
                float w = W1[(HH + d)*MLPD + m];
                e0 = fmaf(Wd[0*DIRD + d], w, e0);
                e1 = fmaf(Wd[1*DIRD + d], w, e1);
                e2 = fmaf(Wd[2*DIRD + d], w, e2);
                e3 = fmaf(Wd[3*DIRD + d], w, e3);
                c  = fmaf(bd[d],          w, c);
            }
            g_E[0*MLPD + m] = e0;
            g_E[1*MLPD + m] = e1;
            g_E[2*MLPD + m] = e2;
            g_E[3*MLPD + m] = e3;
            g_c0[m] = c;
        }
        return;
    }

    extern __shared__ float qs[];
    float* sWq = qs;
    float* sWk = qs + HH*HH;
    float* sWv = qs + 2*HH*HH;
    float* sF  = qs + 3*HH*HH;
    const int row0 = blockIdx.x * QKV_ROWS;

    for (int idx = t; idx < HH*HH; idx += 256) {
        sWq[idx] = Wq[idx];
        sWk[idx] = Wk[idx];
        sWv[idx] = Wv[idx];
    }
    for (int idx = t; idx < QKV_ROWS*HH; idx += 256)
        sF[idx] = feat[row0*HH + idx];
    __syncthreads();

    const int h = t & 63;
    const int rg = t >> 6;               // 4 groups x 2 rows
    float aq[2], ak[2], av[2];
    float vbq = bq[h], vbk = bk[h], vbv = bv[h];
#pragma unroll
    for (int r = 0; r < 2; ++r) { aq[r] = vbq; ak[r] = vbk; av[r] = vbv; }
#pragma unroll 8
    for (int k = 0; k < HH; ++k) {
        float wq = sWq[k*HH + h], wk = sWk[k*HH + h], wv = sWv[k*HH + h];
#pragma unroll
        for (int r = 0; r < 2; ++r) {
            float f = sF[(rg*2 + r)*HH + k];
            aq[r] = fmaf(f, wq, aq[r]);
            ak[r] = fmaf(f, wk, ak[r]);
            av[r] = fmaf(f, wv, av[r]);
        }
    }
#pragma unroll
    for (int r = 0; r < 2; ++r) {
        int row = row0 + rg*2 + r;
        g_Q[row*HH + h]  = aq[r];
        g_Kh[row*HH + h] = __float2half_rn(ak[r]);
        g_V[row*HH + h]  = av[r];
    }
}

// ---------------------------------------------------------------------------
// Kernel 2: scores. Per (b,i): fp16 mma (m16n8k16) GEMM, 2 j-passes of 256,
// warp tile 64 j-rows x 32 m. 2 CTAs/SM. Writes raw scores to g_S.
// ---------------------------------------------------------------------------
#define LDH 72                       // padded row stride in halves (144 B)
#define SA_OFF   0                   // 256*72*2 = 36864
#define SB_OFF   36864               // 128*72*2 = 18432 -> 55296
#define FE_OFF   55296               // 128*16   = 2048  -> 57344
#define SP_OFF   57344               // 4*256*4  = 4096  -> 61440
#define SQ_OFF   61440               // 64*4     = 256   -> 61696
#define SC_TOTAL 61696

__global__ void __launch_bounds__(256, 2)
scores_kernel(const float* __restrict__ wind, const float* __restrict__ loc,
              const float* __restrict__ W1, const float* __restrict__ W2) {
    extern __shared__ __align__(16) char sm[];
    __half*  sA  = (__half*)(sm + SA_OFF);
    __half*  sB  = (__half*)(sm + SB_OFF);
    float4*  sFE = (float4*)(sm + FE_OFF);
    float*   sP  = (float*)(sm + SP_OFF);
    float*   sQ  = (float*)(sm + SQ_OFF);

    const int t    = threadIdx.x;
    const int wid  = t >> 5;
    const int lane = t & 31;
    const int blk  = blockIdx.x;
    const int b    = blk >> 9;
    const int i    = blk & (NN - 1);
    const int bN   = b * NN;

    // per-i epilogue constants
    if (t < MLPD) {
        float li0 = loc[i*2 + 0], li1 = loc[i*2 + 1];
        float w0  = wind[(bN + i)*2 + 0], w1v = wind[(bN + i)*2 + 1];
        float e0 = g_E[t], e1 = g_E[MLPD + t], e2 = g_E[2*MLPD + t], e3 = g_E[3*MLPD + t];
        float f  = g_c0[t] - li0*e0 - li1*e1 + w0*e2 + w1v*e3;
        sFE[t] = make_float4(f, e0, e1, W2[t]);
    }
    if (t < HH) sQ[t] = g_Q[(bN + i)*HH + t];
    __syncthreads();

    // stage B[m][h] = f16(W1[h,m] * Q[i,h])
    for (int idx = t; idx < HH*MLPD; idx += 256) {
        int h = idx >> 7, m = idx & 127;
        sB[m*LDH + h] = __float2half_rn(W1[h*MLPD + m] * sQ[h]);
    }

    const int wj  = wid >> 2;      // 0..1  (j 128-row half of the pass)
    const int wm  = wid & 3;       // 0..3  (m block of 32)
    const int g   = lane >> 2;
    const int tig = lane & 3;
    const float2* loc2 = (const float2*)loc;

#pragma unroll
    for (int p = 0; p < 2; ++p) {
        // stage A = g_Kh rows [p*256, p*256+256) (pure 16B copies)
        const __half* Kbh = &g_Kh[(bN + p*256)*HH];
        for (int idx = t; idx < 256*8; idx += 256) {
            int row = idx >> 3, c8 = idx & 7;
            uint4 v = *(const uint4*)&Kbh[row*HH + c8*8];
            *(uint4*)&sA[row*LDH + c8*8] = v;
        }
        __syncthreads();   // A ready; B ready (p=0); prior pass fully drained

#pragma unroll
        for (int tj = 0; tj < 2; ++tj) {
            const int rowb = wj*128 + tj*64;
            float d[4][4][4];
#pragma unroll
            for (int mi = 0; mi < 4; ++mi)
#pragma unroll
                for (int ni = 0; ni < 4; ++ni)
#pragma unroll
                    for (int r = 0; r < 4; ++r) d[mi][ni][r] = 0.f;

#pragma unroll
            for (int kc = 0; kc < 4; ++kc) {     // 4 chunks of k=16
                const int k0 = kc*16 + tig*2;
                uint32_t Af[4][4];
#pragma unroll
                for (int mi = 0; mi < 4; ++mi) {
                    int r0 = rowb + mi*16 + g;
                    Af[mi][0] = *(const uint32_t*)&sA[r0*LDH + k0];
                    Af[mi][1] = *(const uint32_t*)&sA[(r0 + 8)*LDH + k0];
                    Af[mi][2] = *(const uint32_t*)&sA[r0*LDH + k0 + 8];
                    Af[mi][3] = *(const uint32_t*)&sA[(r0 + 8)*LDH + k0 + 8];
                }
                uint32_t Bf[4][2];
#pragma unroll
                for (int ni = 0; ni < 4; ++ni) {
                    int n = wm*32 + ni*8 + g;
                    Bf[ni][0] = *(const uint32_t*)&sB[n*LDH + k0];
                    Bf[ni][1] = *(const uint32_t*)&sB[n*LDH + k0 + 8];
                }
#pragma unroll
                for (int mi = 0; mi < 4; ++mi)
#pragma unroll
                    for (int ni = 0; ni < 4; ++ni)
                        mma_f16(d[mi][ni], Af[mi], Bf[ni]);
            }

            // in-register epilogue: relu(S + f + loc_j . e) . W2
#pragma unroll
            for (int mi = 0; mi < 4; ++mi) {
                int jl = rowb + mi*16 + g;
                int jg = p*256 + jl;
                float2 l0 = __ldg(&loc2[jg]);
                float2 l1 = __ldg(&loc2[jg + 8]);
                float p0 = 0.f, p1 = 0.f;
#pragma unroll
                for (int ni = 0; ni < 4; ++ni) {
                    int m0 = wm*32 + ni*8 + 2*tig;
                    float4 f0 = sFE[m0], f1 = sFE[m0 + 1];
                    float v;
                    v = d[mi][ni][0] + f0.x + l0.x*f0.y + l0.y*f0.z; p0 = fmaf(fmaxf(v, 0.f), f0.w, p0);
                    v = d[mi][ni][1] + f1.x + l0.x*f1.y + l0.y*f1.z; p0 = fmaf(fmaxf(v, 0.f), f1.w, p0);
                    v = d[mi][ni][2] + f0.x + l1.x*f0.y + l1.y*f0.z; p1 = fmaf(fmaxf(v, 0.f), f0.w, p1);
                    v = d[mi][ni][3] + f1.x + l1.x*f1.y + l1.y*f1.z; p1 = fmaf(fmaxf(v, 0.f), f1.w, p1);
                }
                p0 += __shfl_xor_sync(0xffffffffu, p0, 1);
                p0 += __shfl_xor_sync(0xffffffffu, p0, 2);
                p1 += __shfl_xor_sync(0xffffffffu, p1, 1);
                p1 += __shfl_xor_sync(0xffffffffu, p1, 2);
                if (tig == 0) {
                    sP[wm*256 + jl]     = p0;
                    sP[wm*256 + jl + 8] = p1;
                }
            }
        }
        __syncthreads();
        // combine 4 m-block partials, write raw scores
        float s = sP[t] + sP[256 + t] + sP[512 + t] + sP[768 + t];
        g_S[(size_t)blk*NN + p*256 + t] = s;
    }
}

// ---------------------------------------------------------------------------
// Kernel 3: batched softmax + attn@V. 8 i's per block (grid 256, 256 thr,
// 4 CTAs/SM). One warp per row; V in 64-row tiles, cp.async double-buffered.
// ---------------------------------------------------------------------------
#define IB 8
#define VT 64                                 // V tile rows
#define AV_SMEM (IB*NN*4 + 2*VT*HH*4)         // 16384 + 32768 = 49152
__global__ void __launch_bounds__(256)
smax_av_kernel(float* __restrict__ out) {
    extern __shared__ __align__(16) float avs[];
    float* sS = avs;                  // [IB][NN]
    float* sV = avs + IB*NN;          // [2][VT][HH]

    const int t    = threadIdx.x;
    const int wid  = t >> 5;          // 0..7 = row
    const int lane = t & 31;
    const int b    = blockIdx.x >> 6;         // 64 i-groups per batch
    const int i0   = (blockIdx.x & 63) * IB;
    const int bN   = b * NN;
    const uint32_t svb = smem_u32(sV);

    // prefetch V tile 0 (64 rows x 64 f32 = 16 KB; 4 x 16B per thread)
    {
        const char* src = (const char*)&g_V[bN*HH];
#pragma unroll
        for (int k = 0; k < 4; ++k) {
            int idx = t + k*256;
            CP_A16(svb + idx*16, src + idx*16);
        }
        CP_COMMIT();
    }

    // load 8 rows of raw scores (float4, coalesced)
    {
        const float4* src = (const float4*)&g_S[((size_t)bN + i0) * NN];
        float4* dst = (float4*)sS;
#pragma unroll
        for (int k = 0; k < 4; ++k) dst[t + k*256] = src[t + k*256];
    }
    __syncthreads();

    // per-row softmax: warp wid owns row wid; inv stays in-register
    float inv;
    {
        float* r = &sS[wid*NN];
        float m = -1e30f;
#pragma unroll
        for (int c = 0; c < NN/32; ++c) m = fmaxf(m, r[c*32 + lane]);
#pragma unroll
        for (int o = 16; o > 0; o >>= 1) m = fmaxf(m, __shfl_xor_sync(0xffffffffu, m, o));
        float sum = 0.f;
#pragma unroll
        for (int c = 0; c < NN/32; ++c) {
            float e = __expf(r[c*32 + lane] - m);
            r[c*32 + lane] = e;
            sum += e;
        }
#pragma unroll
        for (int o = 16; o > 0; o >>= 1) sum += __shfl_xor_sync(0xffffffffu, sum, o);
        inv = 1.f / sum;
    }

    // AV over 8 V tiles (double-buffered)
    const int h4 = lane & 15;
    const int jh = lane >> 4;
    float4 acc = make_float4(0.f, 0.f, 0.f, 0.f);

#pragma unroll
    for (int jt = 0; jt < NN/VT; ++jt) {
        if (jt + 1 < NN/VT) {
            const char* src = (const char*)&g_V[(bN + (jt + 1)*VT)*HH];
            uint32_t dstb = svb + ((jt + 1) & 1) * (VT*HH*4);
#pragma unroll
            for (int k = 0; k < 4; ++k) {
                int idx = t + k*256;
                CP_A16(dstb + idx*16, src + idx*16);
            }
            CP_COMMIT();
            CP_WAIT(1);
        } else {
            CP_WAIT(0);
        }
        __syncthreads();
        const float*  Prow = &sS[wid*NN + jt*VT + jh*32];
        const float4* V4   = (const float4*)&sV[(jt & 1)*VT*HH];
#pragma unroll 4
        for (int j = 0; j < 32; ++j) {
            float p = Prow[j];
            float4 v = V4[(jh*32 + j)*16 + h4];
            acc.x = fmaf(p, v.x, acc.x);
            acc.y = fmaf(p, v.y, acc.y);
            acc.z = fmaf(p, v.z, acc.z);
            acc.w = fmaf(p, v.w, acc.w);
        }
        __syncthreads();
    }

    // combine j-halves (lane ^ 16); lanes < 16 write
    acc.x += __shfl_xor_sync(0xffffffffu, acc.x, 16);
    acc.y += __shfl_xor_sync(0xffffffffu, acc.y, 16);
    acc.z += __shfl_xor_sync(0xffffffffu, acc.z, 16);
    acc.w += __shfl_xor_sync(0xffffffffu, acc.w, 16);
    if (jh == 0) {
        acc.x *= inv; acc.y *= inv; acc.z *= inv; acc.w *= inv;
        ((float4*)&out[(bN + i0 + wid)*HH])[h4] = acc;
    }
}

// ---------------------------------------------------------------------------
extern "C" void kernel_launch(void* const* d_in, const int* in_sizes, int n_in,
                              void* d_out, int out_size) {
    const float* features = (const float*)d_in[0];
    const float* wind     = (const float*)d_in[1];
    const float* loc      = (const float*)d_in[2];
    const float* Wq       = (const float*)d_in[3];
    const float* bq       = (const float*)d_in[4];
    const float* Wk       = (const float*)d_in[5];
    const float* bk       = (const float*)d_in[6];
    const float* Wv       = (const float*)d_in[7];
    const float* bv       = (const float*)d_in[8];
    const float* Wd       = (const float*)d_in[9];
    const float* bd       = (const float*)d_in[10];
    const float* W1       = (const float*)d_in[11];
    const float* b1       = (const float*)d_in[12];
    const float* W2       = (const float*)d_in[13];
    // d_in[14] = b2: softmax-invariant -> dropped.
    (void)in_sizes; (void)n_in; (void)out_size;

    cudaFuncSetAttribute(qkv_kernel, cudaFuncAttributeMaxDynamicSharedMemorySize, QKV_SMEM);
    cudaFuncSetAttribute(scores_kernel, cudaFuncAttributeMaxDynamicSharedMemorySize, SC_TOTAL);
    cudaFuncSetAttribute(smax_av_kernel, cudaFuncAttributeMaxDynamicSharedMemorySize, AV_SMEM);

    qkv_kernel<<<BB*NN/QKV_ROWS + 1, 256, QKV_SMEM>>>(features, Wq, bq, Wk, bk, Wv, bv,
                                                      Wd, bd, W1, b1);
    scores_kernel<<<BB*NN, 256, SC_TOTAL>>>(wind, loc, W1, W2);
    smax_av_kernel<<<BB*NN/IB, 256, AV_SMEM>>>((float*)d_out);
}